// round 9
// baseline (speedup 1.0000x reference)
#include <cuda_runtime.h>
#include <math.h>
#include <limits.h>

#define BATCH 4096
#define DIM   512
#define NCLS  128
#define BPC   8                  // blocks per class
#define NBLK  (NCLS * BPC)       // 1024
#define THR   128
#define CH    8                  // smem chunk rows
#define MAXM  128                // member cap (random 4096->128: max ~60)
#define AR    4                  // anchors per block (shared by all warps)

__device__ double g_partial[NBLK];
__device__ int    g_pcount[NBLK];
__device__ int    g_done;        // zero-init; last block resets each run

__global__ void __launch_bounds__(THR, 8) k_all(
    const float* __restrict__ batch,
    const int*   __restrict__ labels,
    const int*   __restrict__ anchors,
    const int*   __restrict__ negatives,
    float*       __restrict__ out)
{
    const int c    = blockIdx.x >> 3;
    const int oct  = blockIdx.x & 7;
    const int tid  = threadIdx.x;
    const int lane = tid & 31;
    const int wid  = tid >> 5;             // 0..3

    __shared__ __align__(16) float sh_rows[CH][DIM];   // 16 KB
    __shared__ __align__(16) float sh_a[AR][DIM];      // 8 KB
    __shared__ int    sh_raw[MAXM];
    __shared__ int    sh_memb[MAXM];       // sorted: canonical across the class's 8 blocks
    __shared__ float  sh_bk[4][AR];
    __shared__ int    sh_bj[4][AR];
    __shared__ double sh_ws[4];
    __shared__ int    sh_wc[4];
    __shared__ int    sh_cnt, sh_last;

    // ---- build member list (order nondeterministic) ----
    if (tid == 0) sh_cnt = 0;
    __syncthreads();
    for (int s = tid; s < BATCH; s += THR) {
        if (labels[s] == c) {
            int pos = atomicAdd(&sh_cnt, 1);
            if (pos < MAXM) sh_raw[pos] = s;
        }
    }
    __syncthreads();
    const int cnt = min(sh_cnt, MAXM);

    // ---- rank-sort ascending: canonical slot partition across blocks ----
    for (int t = tid; t < cnt; t += THR) {
        int v = sh_raw[t];
        int rank = 0;
        for (int k = 0; k < cnt; ++k) rank += (sh_raw[k] < v);
        sh_memb[rank] = v;
    }
    __syncthreads();

    double wsum = 0.0;
    int    wcnt = 0;

    if (cnt >= 3) {   // valid iff (cnt-1) > 1
        const int npass  = (cnt + 31) >> 5;            // 8 blocks x 4 anchors = 32 ranks/pass
        const int nchunk = (cnt + CH - 1) / CH;

        for (int pass = 0; pass < npass; ++pass) {
            int  am[AR]; bool av[AR];
            #pragma unroll
            for (int r = 0; r < AR; ++r) {
                int m = pass * 32 + oct * AR + r;
                av[r] = (m < cnt);
                am[r] = av[r] ? sh_memb[m] : -1;
            }
            // stage the 4 anchor rows: warp r loads row r (float4)
            __syncthreads();
            if (av[wid]) {
                const float4* src = (const float4*)(batch + (size_t)am[wid] * DIM);
                float4*       dst = (float4*)&sh_a[wid][0];
                #pragma unroll
                for (int k = 0; k < 4; ++k) dst[lane + 32 * k] = src[lane + 32 * k];
            }
            __syncthreads();
            // every warp copies all 4 anchors to registers
            float areg[AR][16];
            #pragma unroll
            for (int r = 0; r < AR; ++r)
                #pragma unroll
                for (int k = 0; k < 16; ++k) areg[r][k] = sh_a[r][lane + 32 * k];

            float bestk[AR]; int bestj[AR];
            #pragma unroll
            for (int r = 0; r < AR; ++r) { bestk[r] = INFINITY; bestj[r] = INT_MAX; }

            for (int chb = 0; chb < nchunk; ++chb) {
                const int base = chb * CH;
                const int nrow = min(CH, cnt - base);
                __syncthreads();
                {   // coop chunk load: 16 threads/row, float4
                    int row = tid >> 4, sub = tid & 15;
                    if (row < nrow) {
                        const float4* src = (const float4*)(batch + (size_t)sh_memb[base + row] * DIM);
                        float4*       dst = (float4*)&sh_rows[row][0];
                        #pragma unroll
                        for (int k = 0; k < 8; ++k) dst[sub + 16 * k] = src[sub + 16 * k];
                    }
                }
                __syncthreads();

                for (int q = wid; q < nrow; q += 4) {
                    const int j = sh_memb[base + q];
                    float bv[16];
                    #pragma unroll
                    for (int k = 0; k < 16; ++k) bv[k] = sh_rows[q][lane + 32 * k];
                    float d0 = 0.f, d1 = 0.f, d2 = 0.f, d3 = 0.f, sqb = 0.f;
                    #pragma unroll
                    for (int k = 0; k < 16; ++k) {
                        float b = bv[k];
                        d0  = fmaf(areg[0][k], b, d0);
                        d1  = fmaf(areg[1][k], b, d1);
                        d2  = fmaf(areg[2][k], b, d2);
                        d3  = fmaf(areg[3][k], b, d3);
                        sqb = fmaf(b, b, sqb);
                    }
                    #pragma unroll
                    for (int o = 16; o; o >>= 1) {
                        d0  += __shfl_xor_sync(0xFFFFFFFFu, d0, o);
                        d1  += __shfl_xor_sync(0xFFFFFFFFu, d1, o);
                        d2  += __shfl_xor_sync(0xFFFFFFFFu, d2, o);
                        d3  += __shfl_xor_sync(0xFFFFFFFFu, d3, o);
                        sqb += __shfl_xor_sync(0xFFFFFFFFu, sqb, o);
                    }
                    float kk[AR];
                    kk[0] = fmaf(-2.f, d0, sqb);
                    kk[1] = fmaf(-2.f, d1, sqb);
                    kk[2] = fmaf(-2.f, d2, sqb);
                    kk[3] = fmaf(-2.f, d3, sqb);
                    #pragma unroll
                    for (int r = 0; r < AR; ++r) {
                        if (j != am[r] && (kk[r] < bestk[r] || (kk[r] == bestk[r] && j < bestj[r]))) {
                            bestk[r] = kk[r]; bestj[r] = j;
                        }
                    }
                }
            }

            // ---- combine warp bests per anchor ----
            if (lane < AR) { sh_bk[wid][lane] = 0.f; }   // touch to keep layout live
            #pragma unroll
            for (int r = 0; r < AR; ++r) {
                if (lane == 0) { sh_bk[wid][r] = bestk[r]; sh_bj[wid][r] = bestj[r]; }
            }
            __syncthreads();

            // ---- epilogue: warp r handles anchor r ----
            #pragma unroll
            for (int r = 0; r < AR; ++r) {
                if (r != wid || !av[r]) continue;
                float bk = sh_bk[0][r]; int bj = sh_bj[0][r];
                #pragma unroll
                for (int w = 1; w < 4; ++w) {
                    float k2 = sh_bk[w][r]; int j2 = sh_bj[w][r];
                    if (k2 < bk || (k2 == bk && j2 < bj)) { bk = k2; bj = j2; }
                }
                const int t_   = am[r];
                const int a    = anchors[t_];
                const int nidx = negatives[t_];
                const int p    = bj;
                const float* pr_ = batch + (size_t)p * DIM;
                const float* nr_ = batch + (size_t)nidx * DIM;
                float a1 = 0.f, a2 = 0.f;
                if (a == t_) {   // anchor row in registers
                    #pragma unroll
                    for (int k = 0; k < 16; ++k) {
                        float va = areg[r][k];
                        float e1 = va - pr_[lane + 32 * k];
                        float e2 = va - nr_[lane + 32 * k];
                        a1 = fmaf(e1, e1, a1); a2 = fmaf(e2, e2, a2);
                    }
                } else {         // general path (kept for correctness)
                    const float* ar_ = batch + (size_t)a * DIM;
                    #pragma unroll
                    for (int k = 0; k < 16; ++k) {
                        float va = ar_[lane + 32 * k];
                        float e1 = va - pr_[lane + 32 * k];
                        float e2 = va - nr_[lane + 32 * k];
                        a1 = fmaf(e1, e1, a1); a2 = fmaf(e2, e2, a2);
                    }
                }
                #pragma unroll
                for (int o = 16; o; o >>= 1) {
                    a1 += __shfl_xor_sync(0xFFFFFFFFu, a1, o);
                    a2 += __shfl_xor_sync(0xFFFFFFFFu, a2, o);
                }
                if (lane == 0) {
                    float d_ap = sqrtf(fmaxf(a1, 1e-12f));   // matches _pair_dist
                    float d_an = sqrtf(fmaxf(a2, 1e-12f));
                    float x    = (d_ap - d_an) * 10.f;       // (s_an-s_ap)/TEMP
                    float per  = fmaxf(x, 0.f) + log1pf(expf(-fabsf(x)));
                    wsum += (double)per; wcnt += 1;
                }
            }
        }
    }

    if (lane == 0) { sh_ws[wid] = wsum; sh_wc[wid] = wcnt; }
    __syncthreads();
    if (tid == 0) {
        double s = sh_ws[0] + sh_ws[1] + sh_ws[2] + sh_ws[3];
        int    n = sh_wc[0] + sh_wc[1] + sh_wc[2] + sh_wc[3];
        g_partial[blockIdx.x] = s;
        g_pcount[blockIdx.x]  = n;
        __threadfence();
        int old = atomicAdd(&g_done, 1);
        sh_last = (old == NBLK - 1);
    }
    __syncthreads();

    // ---- last block reduces all partials (single launch) ----
    if (sh_last) {
        double s = 0.0; int n = 0;
        for (int t2 = tid; t2 < NBLK; t2 += THR) { s += g_partial[t2]; n += g_pcount[t2]; }
        #pragma unroll
        for (int o = 16; o; o >>= 1) {
            s += __shfl_xor_sync(0xFFFFFFFFu, s, o);
            n += __shfl_xor_sync(0xFFFFFFFFu, n, o);
        }
        if (lane == 0) { sh_ws[wid] = s; sh_wc[wid] = n; }
        __syncthreads();
        if (tid == 0) {
            double ts = sh_ws[0] + sh_ws[1] + sh_ws[2] + sh_ws[3];
            int    tn = sh_wc[0] + sh_wc[1] + sh_wc[2] + sh_wc[3];
            out[0] = (float)(ts / (double)tn);
            g_done = 0;   // reset for next graph replay
        }
    }
}

extern "C" void kernel_launch(void* const* d_in, const int* in_sizes, int n_in,
                              void* d_out, int out_size) {
    const float* batch     = (const float*)d_in[0];
    const int*   labels    = (const int*)d_in[1];
    const int*   anchors   = (const int*)d_in[2];
    const int*   negatives = (const int*)d_in[3];
    float* out = (float*)d_out;

    k_all<<<NBLK, THR>>>(batch, labels, anchors, negatives, out);
}

// round 11
// speedup vs baseline: 1.6644x; 1.6644x over previous
#include <cuda_runtime.h>
#include <math.h>
#include <limits.h>

#define BATCH 4096
#define DIM   512
#define NCLS  128
#define BPC   4                   // blocks per class
#define NBLK  (NCLS * BPC)        // 512
#define THR   128
#define MAXM  128                 // member cap (binomial(4096,1/128): max ~66)
#define AW    2                   // anchors per warp

__device__ double g_partial[NBLK];
__device__ int    g_pcount[NBLK];
__device__ int    g_done;         // zero-init; last block resets each run

__device__ __forceinline__ float wsum32(float v) {
    #pragma unroll
    for (int o = 16; o; o >>= 1) v += __shfl_xor_sync(0xFFFFFFFFu, v, o);
    return v;
}

__global__ void __launch_bounds__(THR) k_main(
    const float* __restrict__ batch,
    const int*   __restrict__ labels,
    const int*   __restrict__ anchors,
    const int*   __restrict__ negatives,
    float*       __restrict__ out)
{
    const int c   = blockIdx.x >> 2;
    const int qb  = blockIdx.x & 3;
    const int tid = threadIdx.x;
    const int lane = tid & 31;
    const int wid  = tid >> 5;             // 0..3
    const int wslot = qb * 4 + wid;        // 0..15 warp slot within class

    __shared__ int    sh_raw[MAXM];
    __shared__ int    sh_memb[MAXM];       // rank-sorted: canonical across sibling blocks
    __shared__ double sh_ws[4];
    __shared__ int    sh_wc[4];
    __shared__ int    sh_cnt, sh_last;

    // ---- build member list (atomic order nondeterministic) ----
    if (tid == 0) sh_cnt = 0;
    __syncthreads();
    for (int s = tid; s < BATCH; s += THR) {
        if (labels[s] == c) {
            int pos = atomicAdd(&sh_cnt, 1);
            if (pos < MAXM) sh_raw[pos] = s;
        }
    }
    __syncthreads();
    const int cnt = min(sh_cnt, MAXM);

    // ---- rank-sort ascending: canonical anchor partition across the 4 blocks ----
    for (int t = tid; t < cnt; t += THR) {
        int v = sh_raw[t];
        int rank = 0;
        for (int k = 0; k < cnt; ++k) rank += (sh_raw[k] < v);
        sh_memb[rank] = v;
    }
    __syncthreads();                       // last barrier before the end

    double wsum = 0.0;
    int    wcnt = 0;

    if (cnt >= 3) {                        // valid iff (cnt-1) > 1
        // warp owns slots {base, base+1}, striding by 32 slots per pass
        for (int base = wslot * AW; base < cnt; base += 16 * AW) {
            const int  am0 = sh_memb[base];
            const bool v1  = (base + 1 < cnt);
            const int  am1 = v1 ? sh_memb[base + 1] : -1;

            // a2 = 2*anchor_row (key = sum b*(b-2a)); a recovered as 0.5*a2 (exact)
            float a20[16], a21[16];
            {
                const float4* s0 = (const float4*)(batch + (size_t)am0 * DIM);
                #pragma unroll
                for (int k = 0; k < 4; ++k) {
                    float4 v = s0[lane + 32 * k];
                    a20[4*k+0] = 2.f*v.x; a20[4*k+1] = 2.f*v.y;
                    a20[4*k+2] = 2.f*v.z; a20[4*k+3] = 2.f*v.w;
                }
                const float4* s1 = (const float4*)(batch + (size_t)(v1 ? am1 : am0) * DIM);
                #pragma unroll
                for (int k = 0; k < 4; ++k) {
                    float4 v = s1[lane + 32 * k];
                    a21[4*k+0] = 2.f*v.x; a21[4*k+1] = 2.f*v.y;
                    a21[4*k+2] = 2.f*v.z; a21[4*k+3] = 2.f*v.w;
                }
            }

            float bk0 = INFINITY, bk1 = INFINITY;
            int   bj0 = INT_MAX,  bj1 = INT_MAX;

            // prefetch first member row
            int jn = sh_memb[0];
            float4 nxt0, nxt1, nxt2, nxt3;
            {
                const float4* sp = (const float4*)(batch + (size_t)jn * DIM);
                nxt0 = sp[lane]; nxt1 = sp[lane + 32]; nxt2 = sp[lane + 64]; nxt3 = sp[lane + 96];
            }

            for (int m = 0; m < cnt; ++m) {
                const int j = jn;
                float4 c0 = nxt0, c1 = nxt1, c2 = nxt2, c3 = nxt3;
                if (m + 1 < cnt) {
                    jn = sh_memb[m + 1];
                    const float4* sp = (const float4*)(batch + (size_t)jn * DIM);
                    nxt0 = sp[lane]; nxt1 = sp[lane + 32]; nxt2 = sp[lane + 64]; nxt3 = sp[lane + 96];
                }
                float k0 = 0.f, k1 = 0.f;
                const float b[16] = {c0.x,c0.y,c0.z,c0.w, c1.x,c1.y,c1.z,c1.w,
                                     c2.x,c2.y,c2.z,c2.w, c3.x,c3.y,c3.z,c3.w};
                #pragma unroll
                for (int k = 0; k < 16; ++k) {
                    k0 = fmaf(b[k], b[k] - a20[k], k0);
                    k1 = fmaf(b[k], b[k] - a21[k], k1);
                }
                #pragma unroll
                for (int o = 16; o; o >>= 1) {
                    k0 += __shfl_xor_sync(0xFFFFFFFFu, k0, o);
                    k1 += __shfl_xor_sync(0xFFFFFFFFu, k1, o);
                }
                if (j != am0 && (k0 < bk0 || (k0 == bk0 && j < bj0))) { bk0 = k0; bj0 = j; }
                if (v1 && j != am1 && (k1 < bk1 || (k1 == bk1 && j < bj1))) { bk1 = k1; bj1 = j; }
            }

            // ---- epilogue: d_ap, d_an via direct diff (matches _pair_dist) ----
            #pragma unroll
            for (int r = 0; r < AW; ++r) {
                if (r == 1 && !v1) break;
                const int   t_  = (r == 0) ? am0 : am1;
                const int   p   = (r == 0) ? bj0 : bj1;
                const float* a2 = (r == 0) ? a20 : a21;
                const int   a    = anchors[t_];
                const int   nidx = negatives[t_];
                const float4* pp = (const float4*)(batch + (size_t)p * DIM);
                const float4* np = (const float4*)(batch + (size_t)nidx * DIM);
                float s1 = 0.f, s2 = 0.f;
                if (a == t_) {
                    #pragma unroll
                    for (int k = 0; k < 4; ++k) {
                        float4 pv = pp[lane + 32 * k], nv = np[lane + 32 * k];
                        float va0 = 0.5f*a2[4*k+0], va1 = 0.5f*a2[4*k+1];
                        float va2 = 0.5f*a2[4*k+2], va3 = 0.5f*a2[4*k+3];
                        float e;
                        e = va0 - pv.x; s1 = fmaf(e,e,s1); e = va0 - nv.x; s2 = fmaf(e,e,s2);
                        e = va1 - pv.y; s1 = fmaf(e,e,s1); e = va1 - nv.y; s2 = fmaf(e,e,s2);
                        e = va2 - pv.z; s1 = fmaf(e,e,s1); e = va2 - nv.z; s2 = fmaf(e,e,s2);
                        e = va3 - pv.w; s1 = fmaf(e,e,s1); e = va3 - nv.w; s2 = fmaf(e,e,s2);
                    }
                } else {   // general path (kept for correctness)
                    const float4* ap = (const float4*)(batch + (size_t)a * DIM);
                    #pragma unroll
                    for (int k = 0; k < 4; ++k) {
                        float4 av = ap[lane + 32 * k], pv = pp[lane + 32 * k], nv = np[lane + 32 * k];
                        float e;
                        e = av.x - pv.x; s1 = fmaf(e,e,s1); e = av.x - nv.x; s2 = fmaf(e,e,s2);
                        e = av.y - pv.y; s1 = fmaf(e,e,s1); e = av.y - nv.y; s2 = fmaf(e,e,s2);
                        e = av.z - pv.z; s1 = fmaf(e,e,s1); e = av.z - nv.z; s2 = fmaf(e,e,s2);
                        e = av.w - pv.w; s1 = fmaf(e,e,s1); e = av.w - nv.w; s2 = fmaf(e,e,s2);
                    }
                }
                s1 = wsum32(s1); s2 = wsum32(s2);
                if (lane == 0) {
                    float d_ap = sqrtf(fmaxf(s1, 1e-12f));
                    float d_an = sqrtf(fmaxf(s2, 1e-12f));
                    float x    = (d_ap - d_an) * 10.f;      // (s_an-s_ap)/TEMP
                    float per  = fmaxf(x, 0.f) + log1pf(expf(-fabsf(x)));
                    wsum += (double)per; wcnt += 1;
                }
            }
        }
    }

    if (lane == 0) { sh_ws[wid] = wsum; sh_wc[wid] = wcnt; }
    __syncthreads();
    if (tid == 0) {
        double s = sh_ws[0] + sh_ws[1] + sh_ws[2] + sh_ws[3];
        int    n = sh_wc[0] + sh_wc[1] + sh_wc[2] + sh_wc[3];
        g_partial[blockIdx.x] = s;
        g_pcount[blockIdx.x]  = n;
        __threadfence();
        int old = atomicAdd(&g_done, 1);
        sh_last = (old == NBLK - 1);
    }
    __syncthreads();

    // ---- last block reduces all partials (single launch) ----
    if (sh_last) {
        double s = 0.0; int n = 0;
        for (int t2 = tid; t2 < NBLK; t2 += THR) { s += g_partial[t2]; n += g_pcount[t2]; }
        #pragma unroll
        for (int o = 16; o; o >>= 1) {
            s += __shfl_xor_sync(0xFFFFFFFFu, s, o);
            n += __shfl_xor_sync(0xFFFFFFFFu, n, o);
        }
        if (lane == 0) { sh_ws[wid] = s; sh_wc[wid] = n; }
        __syncthreads();
        if (tid == 0) {
            double ts = sh_ws[0] + sh_ws[1] + sh_ws[2] + sh_ws[3];
            int    tn = sh_wc[0] + sh_wc[1] + sh_wc[2] + sh_wc[3];
            out[0] = (float)(ts / (double)tn);
            g_done = 0;   // reset for next graph replay
        }
    }
}

extern "C" void kernel_launch(void* const* d_in, const int* in_sizes, int n_in,
                              void* d_out, int out_size) {
    const float* batch     = (const float*)d_in[0];
    const int*   labels    = (const int*)d_in[1];
    const int*   anchors   = (const int*)d_in[2];
    const int*   negatives = (const int*)d_in[3];
    float* out = (float*)d_out;

    k_main<<<NBLK, THR>>>(batch, labels, anchors, negatives, out);
}